// round 6
// baseline (speedup 1.0000x reference)
#include <cuda_runtime.h>
#include <cuda_bf16.h>
#include <cstdint>

// ---------------- problem constants ----------------
// pred[4096,1000] f32, target[4096] i32-or-i64, adj[8192,8192] f32, emb[8192,256] f32
#define B_ROWS 4096
#define C_CLS  1000
#define NN     8192
#define DD     256

// main kernel tiling (portable tensor path: mma.sync m16n8k16 bf16)
#define MCTA    128                 // adj rows per CTA
#define KSPLIT  2
#define KC      64                  // K per pipeline stage
#define KRANGE  (NN / KSPLIT)       // 4096
#define NIT     (KRANGE / KC)       // 64
#define NCTA    ((NN / MCTA) * KSPLIT)  // 128
#define THREADS 512

// smem: A fp32 [128][68] (pad), B bf16 [256][72] (pad), 3 stages
#define A_STRIDE_F 68
#define B_STRIDE_H 72
#define ASZ (MCTA * A_STRIDE_F * 4)     // 34816
#define BSZ (DD * B_STRIDE_H * 2)       // 36864
#define BOFF (3 * ASZ)                  // 104448
#define SMEM_BYTES (3 * ASZ + 3 * BSZ)  // 215040

// ---------------- device scratch (no allocs allowed) ----------------
__device__ __nv_bfloat16 g_ehatT[(size_t)DD * NN];  // Ê^T [256][8192] bf16
__device__ float g_ce[B_ROWS];
__device__ float g_psem[NCTA];
__device__ float g_pabs[NCTA];
__device__ float g_pplain[NCTA];
__device__ int   g_tgt64;            // 1 if target buffer is int64-laid-out

// ---------------- helpers ----------------
__device__ __forceinline__ uint32_t smem_u32(const void* p) {
    uint32_t a;
    asm("{ .reg .u64 t; cvta.to.shared.u64 t, %1; cvt.u32.u64 %0, t; }" : "=r"(a) : "l"(p));
    return a;
}
__device__ __forceinline__ void cp16(uint32_t s, const void* g) {
    asm volatile("cp.async.cg.shared.global [%0], [%1], 16;" :: "r"(s), "l"(g));
}
__device__ __forceinline__ void cp_commit() {
    asm volatile("cp.async.commit_group;" ::: "memory");
}
__device__ __forceinline__ uint32_t pack_bf16x2(float lo, float hi) {
    __nv_bfloat162 h = __floats2bfloat162_rn(lo, hi);
    return *reinterpret_cast<uint32_t*>(&h);
}
__device__ __forceinline__ void mma_16816(float* d, const uint32_t* a, const uint32_t* b) {
    asm volatile(
        "mma.sync.aligned.m16n8k16.row.col.f32.bf16.bf16.f32 "
        "{%0,%1,%2,%3}, {%4,%5,%6,%7}, {%8,%9}, {%0,%1,%2,%3};"
        : "+f"(d[0]), "+f"(d[1]), "+f"(d[2]), "+f"(d[3])
        : "r"(a[0]), "r"(a[1]), "r"(a[2]), "r"(a[3]), "r"(b[0]), "r"(b[1]));
}

// ---------------- kernel 0: probe target dtype layout ----------------
// Safe under both layouts: reads only the first 4096 int32 words.
// int64 targets (<1000) => every odd word is 0. int32 targets => odd words are
// random values in [0,1000), virtually surely nonzero somewhere.
__global__ void rdl_probe(const int* __restrict__ t) {
    __shared__ int any;
    if (threadIdx.x == 0) any = 0;
    __syncthreads();
    int local = 0;
    for (int i = threadIdx.x; i < 2048; i += blockDim.x) local |= t[2 * i + 1];
    if (local) atomicOr(&any, 1);
    __syncthreads();
    if (threadIdx.x == 0) g_tgt64 = (any == 0) ? 1 : 0;
}

// ---------------- kernel 1: per-row cross-entropy ----------------
__global__ void rdl_ce(const float* __restrict__ pred, const void* __restrict__ tgt) {
    const int row = blockIdx.x;
    const float* p = pred + (size_t)row * C_CLS;
    const int tid = threadIdx.x, lane = tid & 31, wid = tid >> 5;
    __shared__ float smax[8], ssum[8];

    float m = -3.4e38f;
    for (int c = tid; c < C_CLS; c += 256) m = fmaxf(m, p[c]);
#pragma unroll
    for (int o = 16; o; o >>= 1) m = fmaxf(m, __shfl_xor_sync(0xffffffffu, m, o));
    if (lane == 0) smax[wid] = m;
    __syncthreads();
    float bm = smax[0];
#pragma unroll
    for (int w = 1; w < 8; w++) bm = fmaxf(bm, smax[w]);

    float s = 0.f;
    for (int c = tid; c < C_CLS; c += 256) s += expf(p[c] - bm);
#pragma unroll
    for (int o = 16; o; o >>= 1) s += __shfl_xor_sync(0xffffffffu, s, o);
    if (lane == 0) ssum[wid] = s;
    __syncthreads();
    if (tid == 0) {
        float bs = 0.f;
#pragma unroll
        for (int w = 0; w < 8; w++) bs += ssum[w];
        int t;
        if (g_tgt64) t = (int)((const long long*)tgt)[row];
        else         t = ((const int*)tgt)[row];
        t = min(max(t, 0), C_CLS - 1);   // never OOB even on garbage
        g_ce[row] = -(p[t] - bm - logf(bs));
    }
}

// ---------------- kernel 2: norms + transposed normalized embeddings (bf16) ----------------
__global__ void rdl_norm(const float* __restrict__ emb) {
    __shared__ float tile[32 * DD];   // 32 KB
    __shared__ float rnorm[32];
    const int tid = threadIdx.x, lane = tid & 31, wid = tid >> 5;
    const int r0 = blockIdx.x * 32;

    for (int idx = tid; idx < 32 * DD; idx += 256)
        tile[idx] = emb[(size_t)r0 * DD + idx];
    __syncthreads();

#pragma unroll
    for (int q = 0; q < 4; q++) {
        const int rr = wid * 4 + q;
        float s = 0.f;
#pragma unroll
        for (int kk = lane; kk < DD; kk += 32) { float v = tile[rr * DD + kk]; s += v * v; }
#pragma unroll
        for (int o = 16; o; o >>= 1) s += __shfl_xor_sync(0xffffffffu, s, o);
        if (lane == 0) rnorm[rr] = rsqrtf(s);   // norms ~16, never near eps
    }
    __syncthreads();

    const int j = lane;
#pragma unroll
    for (int d8 = 0; d8 < 32; d8++) {
        const int d = d8 * 8 + wid;
        g_ehatT[(size_t)d * NN + r0 + j] = __float2bfloat16(tile[j * DD + d] * rnorm[j]);
    }
}

// ---------------- kernel 3: fused adj stream + mma.sync GEMM + fused contraction ----------------
__device__ __forceinline__ void rdl_issue(int it, int tid, uint32_t sb,
                                          const float* __restrict__ adj,
                                          int row0, int kbase) {
    const int s = it % 3;
    const int kb = kbase + it * KC;
    const uint32_t sa = sb + s * ASZ;
    const uint32_t sbb = sb + BOFF + s * BSZ;
    // A: adj fp32 [128 rows][64 cols] -> 2048 x 16B
#pragma unroll
    for (int i = 0; i < 4; i++) {
        const int idx = tid + (i << 9);
        const int r = idx >> 4, c16 = idx & 15;
        cp16(sa + r * (A_STRIDE_F * 4) + c16 * 16,
             adj + (size_t)(row0 + r) * NN + (unsigned)(kb + c16 * 4));
    }
    // B: ehatT bf16 [256 rows][64 cols] -> 2048 x 16B
#pragma unroll
    for (int i = 0; i < 4; i++) {
        const int idx = tid + (i << 9);
        const int r = idx >> 3, c16 = idx & 7;
        cp16(sbb + r * (B_STRIDE_H * 2) + c16 * 16,
             reinterpret_cast<const char*>(g_ehatT) +
                 ((size_t)r * NN + (unsigned)(kb + c16 * 8)) * 2);
    }
    cp_commit();
}

__global__ __launch_bounds__(THREADS, 1) void rdl_main(const float* __restrict__ adj) {
    extern __shared__ char smem[];
    const int tid = threadIdx.x, wid = tid >> 5, lane = tid & 31;
    const int rb = blockIdx.x & 63;          // 64 row blocks
    const int ks = blockIdx.x >> 6;          // 2 K splits
    const int row0 = rb * MCTA;
    const int kbase = ks * KRANGE;
    const uint32_t sb = smem_u32(smem);

    const int mq = wid & 3;                  // M quadrant (32 rows each)
    const int dq = wid >> 2;                 // D quadrant (64 cols each)
    const int g = lane >> 2, c = lane & 3;

    float acc[2][8][4];
#pragma unroll
    for (int mi = 0; mi < 2; mi++)
#pragma unroll
        for (int ni = 0; ni < 8; ni++)
#pragma unroll
            for (int q = 0; q < 4; q++) acc[mi][ni][q] = 0.f;

    float abs_acc = 0.f, plain_acc = 0.f;

    rdl_issue(0, tid, sb, adj, row0, kbase);
    rdl_issue(1, tid, sb, adj, row0, kbase);

    for (int it = 0; it < NIT; ++it) {
        if (it + 2 < NIT) {
            rdl_issue(it + 2, tid, sb, adj, row0, kbase);
            asm volatile("cp.async.wait_group 2;" ::: "memory");
        } else if (it + 1 < NIT) {
            asm volatile("cp.async.wait_group 1;" ::: "memory");
        } else {
            asm volatile("cp.async.wait_group 0;" ::: "memory");
        }
        __syncthreads();

        const int s = it % 3;
        const float* As = reinterpret_cast<const float*>(smem + s * ASZ);
        const __nv_bfloat16* Bs =
            reinterpret_cast<const __nv_bfloat16*>(smem + BOFF + s * BSZ);

#pragma unroll
        for (int kf = 0; kf < 4; kf++) {
            // B fragments: 8 n-tiles of 8 cols each
            uint32_t bf[8][2];
#pragma unroll
            for (int ni = 0; ni < 8; ni++) {
                const int dr = 64 * dq + 8 * ni + g;
                bf[ni][0] = *reinterpret_cast<const uint32_t*>(Bs + dr * B_STRIDE_H + kf * 16 + 2 * c);
                bf[ni][1] = *reinterpret_cast<const uint32_t*>(Bs + dr * B_STRIDE_H + kf * 16 + 8 + 2 * c);
            }
            // A fragments: 2 m-tiles of 16 rows; fp32 -> bf16; fuse |adj|,sum(adj) (dq==0 only)
            uint32_t af[2][4];
#pragma unroll
            for (int mi = 0; mi < 2; mi++) {
                const int r = 32 * mq + 16 * mi + g;
                const float2 p0 = *reinterpret_cast<const float2*>(As + r * A_STRIDE_F + kf * 16 + 2 * c);
                const float2 p1 = *reinterpret_cast<const float2*>(As + (r + 8) * A_STRIDE_F + kf * 16 + 2 * c);
                const float2 p2 = *reinterpret_cast<const float2*>(As + r * A_STRIDE_F + kf * 16 + 8 + 2 * c);
                const float2 p3 = *reinterpret_cast<const float2*>(As + (r + 8) * A_STRIDE_F + kf * 16 + 8 + 2 * c);
                if (dq == 0) {
                    abs_acc += fabsf(p0.x) + fabsf(p0.y) + fabsf(p1.x) + fabsf(p1.y)
                             + fabsf(p2.x) + fabsf(p2.y) + fabsf(p3.x) + fabsf(p3.y);
                    plain_acc += (p0.x + p0.y) + (p1.x + p1.y) + (p2.x + p2.y) + (p3.x + p3.y);
                }
                af[mi][0] = pack_bf16x2(p0.x, p0.y);
                af[mi][1] = pack_bf16x2(p1.x, p1.y);
                af[mi][2] = pack_bf16x2(p2.x, p2.y);
                af[mi][3] = pack_bf16x2(p3.x, p3.y);
            }
#pragma unroll
            for (int mi = 0; mi < 2; mi++)
#pragma unroll
                for (int ni = 0; ni < 8; ni++)
                    mma_16816(acc[mi][ni], af[mi], bf[ni]);
        }
        __syncthreads();
    }

    // contraction: sem += out[m][d] * ehat[m][d]   (ehat[m][d] = g_ehatT[d][m])
    float sem_acc = 0.f;
#pragma unroll
    for (int mi = 0; mi < 2; mi++)
#pragma unroll
        for (int ni = 0; ni < 8; ni++) {
            const int m0 = row0 + 32 * mq + 16 * mi + g;
            const int d0 = 64 * dq + 8 * ni + 2 * c;
            const float e00 = __bfloat162float(g_ehatT[(size_t)d0 * NN + m0]);
            const float e01 = __bfloat162float(g_ehatT[(size_t)(d0 + 1) * NN + m0]);
            const float e10 = __bfloat162float(g_ehatT[(size_t)d0 * NN + m0 + 8]);
            const float e11 = __bfloat162float(g_ehatT[(size_t)(d0 + 1) * NN + m0 + 8]);
            sem_acc += acc[mi][ni][0] * e00 + acc[mi][ni][1] * e01
                     + acc[mi][ni][2] * e10 + acc[mi][ni][3] * e11;
        }

    // block reduce sem/abs/plain
#pragma unroll
    for (int o = 16; o; o >>= 1) {
        sem_acc   += __shfl_xor_sync(0xffffffffu, sem_acc, o);
        abs_acc   += __shfl_xor_sync(0xffffffffu, abs_acc, o);
        plain_acc += __shfl_xor_sync(0xffffffffu, plain_acc, o);
    }
    float* red = reinterpret_cast<float*>(smem);   // buffers dead now
    __syncthreads();
    if (lane == 0) { red[wid] = sem_acc; red[16 + wid] = abs_acc; red[32 + wid] = plain_acc; }
    __syncthreads();
    if (tid == 0) {
        float s = 0.f, a = 0.f, p = 0.f;
#pragma unroll
        for (int w = 0; w < 16; w++) { s += red[w]; a += red[16 + w]; p += red[32 + w]; }
        g_psem[blockIdx.x] = s; g_pabs[blockIdx.x] = a; g_pplain[blockIdx.x] = p;
    }
}

// ---------------- kernel 4: combine ----------------
__global__ void rdl_combine(float* __restrict__ out) {
    const int tid = threadIdx.x, lane = tid & 31, wid = tid >> 5;
    __shared__ float red[4][8];
    float ce = 0.f, sem = 0.f, ab = 0.f, pl = 0.f;
    for (int i = tid; i < B_ROWS; i += 256) ce += g_ce[i];
    for (int i = tid; i < NCTA; i += 256) { sem += g_psem[i]; ab += g_pabs[i]; pl += g_pplain[i]; }
#pragma unroll
    for (int o = 16; o; o >>= 1) {
        ce  += __shfl_xor_sync(0xffffffffu, ce, o);
        sem += __shfl_xor_sync(0xffffffffu, sem, o);
        ab  += __shfl_xor_sync(0xffffffffu, ab, o);
        pl  += __shfl_xor_sync(0xffffffffu, pl, o);
    }
    if (lane == 0) { red[0][wid] = ce; red[1][wid] = sem; red[2][wid] = ab; red[3][wid] = pl; }
    __syncthreads();
    if (tid == 0) {
        float tce = 0.f, tsem = 0.f, tab = 0.f, tpl = 0.f;
#pragma unroll
        for (int w = 0; w < 8; w++) {
            tce += red[0][w]; tsem += red[1][w]; tab += red[2][w]; tpl += red[3][w];
        }
        const float invB  = 1.0f / (float)B_ROWS;
        const float invN2 = 1.0f / ((float)NN * (float)NN);
        const float l_task   = tce * invB;
        const float l_sparse = tab * invN2;
        const float l_sem    = (tpl - tsem) * invN2;   // mean(adj) - mean(adj*sim)
        out[0] = 1.0f * l_task + 0.01f * l_sparse + 0.1f * l_sem;
    }
}

// ---------------- launch ----------------
extern "C" void kernel_launch(void* const* d_in, const int* in_sizes, int n_in,
                              void* d_out, int out_size) {
    // map inputs by element count (all four are distinct)
    const float* pred = nullptr; const void* tgt = nullptr;
    const float* adj  = nullptr; const float* emb = nullptr;
    for (int i = 0; i < n_in; i++) {
        switch (in_sizes[i]) {
            case B_ROWS * C_CLS:     pred = (const float*)d_in[i]; break;   // 4096000
            case B_ROWS:             tgt  = d_in[i];               break;   // 4096
            case NN * NN:            adj  = (const float*)d_in[i]; break;   // 67108864
            case NN * DD:            emb  = (const float*)d_in[i]; break;   // 2097152
            default: break;
        }
    }
    float* out = (float*)d_out;
    (void)out_size;

    rdl_probe<<<1, 1024>>>((const int*)tgt);
    rdl_ce<<<B_ROWS, 256>>>(pred, tgt);
    rdl_norm<<<NN / 32, 256>>>(emb);
    cudaFuncSetAttribute(rdl_main, cudaFuncAttributeMaxDynamicSharedMemorySize, SMEM_BYTES);
    rdl_main<<<NCTA, THREADS, SMEM_BYTES>>>(adj);
    rdl_combine<<<1, 256>>>(out);
}

// round 7
// speedup vs baseline: 1.1483x; 1.1483x over previous
#include <cuda_runtime.h>
#include <cuda_bf16.h>
#include <cstdint>

// ---------------- problem constants ----------------
#define B_ROWS 4096
#define C_CLS  1000
#define NN     8192
#define DD     256

// main kernel tiling
#define MCTA    128                 // adj rows per CTA
#define KSPLIT  2
#define KC      64                  // K per pipeline stage
#define KRANGE  (NN / KSPLIT)       // 4096
#define NIT     (KRANGE / KC)       // 64
#define NCTA    ((NN / MCTA) * KSPLIT)  // 128
#define THREADS 512

// smem: A fp32 [128][68] x2, B bf16 [256][72] x2, A' bf16 [128][72]
#define A_STRIDE_F 68
#define P_STRIDE_H 72
#define ASZ   (MCTA * A_STRIDE_F * 4)     // 34816
#define BSZ   (DD * P_STRIDE_H * 2)       // 36864
#define BOFF  (2 * ASZ)                   // 69632
#define APOFF (BOFF + 2 * BSZ)            // 143360
#define SMEM_BYTES (APOFF + MCTA * P_STRIDE_H * 2)   // 161792

// ---------------- device scratch ----------------
__device__ __nv_bfloat16 g_ehatT[(size_t)DD * NN];  // Ê^T [256][8192] bf16
__device__ float g_ce[B_ROWS];
__device__ float g_psem[NCTA];
__device__ float g_pabs[NCTA];
__device__ float g_pplain[NCTA];
__device__ int   g_tgt64;

// ---------------- helpers ----------------
__device__ __forceinline__ uint32_t smem_u32(const void* p) {
    uint32_t a;
    asm("{ .reg .u64 t; cvta.to.shared.u64 t, %1; cvt.u32.u64 %0, t; }" : "=r"(a) : "l"(p));
    return a;
}
__device__ __forceinline__ void cp16(uint32_t s, const void* g) {
    asm volatile("cp.async.cg.shared.global [%0], [%1], 16;" :: "r"(s), "l"(g));
}
__device__ __forceinline__ void cp_commit() {
    asm volatile("cp.async.commit_group;" ::: "memory");
}
__device__ __forceinline__ void ldm_x4(uint32_t* r, uint32_t addr) {
    asm volatile("ldmatrix.sync.aligned.m8n8.x4.shared.b16 {%0,%1,%2,%3}, [%4];"
                 : "=r"(r[0]), "=r"(r[1]), "=r"(r[2]), "=r"(r[3]) : "r"(addr));
}
__device__ __forceinline__ void mma_16816(float* d, const uint32_t* a,
                                          uint32_t b0, uint32_t b1) {
    asm volatile(
        "mma.sync.aligned.m16n8k16.row.col.f32.bf16.bf16.f32 "
        "{%0,%1,%2,%3}, {%4,%5,%6,%7}, {%8,%9}, {%0,%1,%2,%3};"
        : "+f"(d[0]), "+f"(d[1]), "+f"(d[2]), "+f"(d[3])
        : "r"(a[0]), "r"(a[1]), "r"(a[2]), "r"(a[3]), "r"(b0), "r"(b1));
}
__device__ __forceinline__ uint32_t pack_bf16x2(float lo, float hi) {
    __nv_bfloat162 h = __floats2bfloat162_rn(lo, hi);
    return *reinterpret_cast<uint32_t*>(&h);
}

// ---------------- kernel 0: probe target dtype layout ----------------
__global__ void rdl_probe(const int* __restrict__ t) {
    __shared__ int any;
    if (threadIdx.x == 0) any = 0;
    __syncthreads();
    int local = 0;
    for (int i = threadIdx.x; i < 2048; i += blockDim.x) local |= t[2 * i + 1];
    if (local) atomicOr(&any, 1);
    __syncthreads();
    if (threadIdx.x == 0) g_tgt64 = (any == 0) ? 1 : 0;
}

// ---------------- kernel 1: per-row cross-entropy ----------------
__global__ void rdl_ce(const float* __restrict__ pred, const void* __restrict__ tgt) {
    const int row = blockIdx.x;
    const float* p = pred + (size_t)row * C_CLS;
    const int tid = threadIdx.x, lane = tid & 31, wid = tid >> 5;
    __shared__ float smax[8], ssum[8];

    float m = -3.4e38f;
    for (int c = tid; c < C_CLS; c += 256) m = fmaxf(m, p[c]);
#pragma unroll
    for (int o = 16; o; o >>= 1) m = fmaxf(m, __shfl_xor_sync(0xffffffffu, m, o));
    if (lane == 0) smax[wid] = m;
    __syncthreads();
    float bm = smax[0];
#pragma unroll
    for (int w = 1; w < 8; w++) bm = fmaxf(bm, smax[w]);

    float s = 0.f;
    for (int c = tid; c < C_CLS; c += 256) s += expf(p[c] - bm);
#pragma unroll
    for (int o = 16; o; o >>= 1) s += __shfl_xor_sync(0xffffffffu, s, o);
    if (lane == 0) ssum[wid] = s;
    __syncthreads();
    if (tid == 0) {
        float bs = 0.f;
#pragma unroll
        for (int w = 0; w < 8; w++) bs += ssum[w];
        int t;
        if (g_tgt64) t = (int)((const long long*)tgt)[row];
        else         t = ((const int*)tgt)[row];
        t = min(max(t, 0), C_CLS - 1);
        g_ce[row] = -(p[t] - bm - logf(bs));
    }
}

// ---------------- kernel 2: norms + transposed normalized embeddings ----------------
__global__ void rdl_norm(const float* __restrict__ emb) {
    __shared__ float tile[32 * DD];
    __shared__ float rnorm[32];
    const int tid = threadIdx.x, lane = tid & 31, wid = tid >> 5;
    const int r0 = blockIdx.x * 32;

    for (int idx = tid; idx < 32 * DD; idx += 256)
        tile[idx] = emb[(size_t)r0 * DD + idx];
    __syncthreads();

#pragma unroll
    for (int q = 0; q < 4; q++) {
        const int rr = wid * 4 + q;
        float s = 0.f;
#pragma unroll
        for (int kk = lane; kk < DD; kk += 32) { float v = tile[rr * DD + kk]; s += v * v; }
#pragma unroll
        for (int o = 16; o; o >>= 1) s += __shfl_xor_sync(0xffffffffu, s, o);
        if (lane == 0) rnorm[rr] = rsqrtf(s);
    }
    __syncthreads();

    const int j = lane;
#pragma unroll
    for (int d8 = 0; d8 < 32; d8++) {
        const int d = d8 * 8 + wid;
        g_ehatT[(size_t)d * NN + r0 + j] = __float2bfloat16(tile[j * DD + d] * rnorm[j]);
    }
}

// ---------------- kernel 3: main fused kernel ----------------
__device__ __forceinline__ void rdl_issue(int it, int tid, uint32_t sb,
                                          const float* __restrict__ adj,
                                          int row0, int kbase) {
    const int s = it & 1;
    const int kb = kbase + it * KC;
    const uint32_t sa = sb + s * ASZ;
    const uint32_t sbb = sb + BOFF + s * BSZ;
    // A: adj fp32 [128 rows][64 cols]
#pragma unroll
    for (int i = 0; i < 4; i++) {
        const int idx = tid + (i << 9);
        const int r = idx >> 4, c16 = idx & 15;
        cp16(sa + r * (A_STRIDE_F * 4) + c16 * 16,
             adj + (size_t)(row0 + r) * NN + (unsigned)(kb + c16 * 4));
    }
    // B: ehatT bf16 [256 rows][64 cols]
#pragma unroll
    for (int i = 0; i < 4; i++) {
        const int idx = tid + (i << 9);
        const int r = idx >> 3, c16 = idx & 7;
        cp16(sbb + r * (P_STRIDE_H * 2) + c16 * 16,
             reinterpret_cast<const char*>(g_ehatT) +
                 ((size_t)r * NN + (unsigned)(kb + c16 * 8)) * 2);
    }
    cp_commit();
}

__global__ __launch_bounds__(THREADS, 1) void rdl_main(const float* __restrict__ adj) {
    extern __shared__ char smem[];
    const int tid = threadIdx.x, wid = tid >> 5, lane = tid & 31;
    const int rb = blockIdx.x & 63;
    const int ks = blockIdx.x >> 6;
    const int row0 = rb * MCTA;
    const int kbase = ks * KRANGE;
    const uint32_t sb = smem_u32(smem);

    const int mq = wid & 3;                  // M quadrant (32 rows)
    const int dq = wid >> 2;                 // D quadrant (64 cols)
    const int g = lane >> 2, c = lane & 3;

    // ldmatrix per-thread address bases (bf16 byte offsets), lane->row mapping
    const int lrow = lane & 15, lcol8 = (lane >> 4) << 3;
    const uint32_t a_base = sb + APOFF +
        (uint32_t)(((32 * mq + lrow) * P_STRIDE_H + lcol8) * 2);
    const uint32_t b_base0 = sb + BOFF +
        (uint32_t)(((64 * dq + lrow) * P_STRIDE_H + lcol8) * 2);

    // conversion-phase indices: 4 float4 chunks per thread
    const int cv_r[4] = { (tid) >> 4, (tid + 512) >> 4, (tid + 1024) >> 4, (tid + 1536) >> 4 };
    const int cv_c = tid & 15;

    float acc[2][8][4];
#pragma unroll
    for (int mi = 0; mi < 2; mi++)
#pragma unroll
        for (int ni = 0; ni < 8; ni++)
#pragma unroll
            for (int q = 0; q < 4; q++) acc[mi][ni][q] = 0.f;

    float abs_acc = 0.f, plain_acc = 0.f;

    rdl_issue(0, tid, sb, adj, row0, kbase);
    rdl_issue(1, tid, sb, adj, row0, kbase);

    for (int it = 0; it < NIT; ++it) {
        const int s = it & 1;
        if (it + 1 < NIT) asm volatile("cp.async.wait_group 1;" ::: "memory");
        else              asm volatile("cp.async.wait_group 0;" ::: "memory");
        __syncthreads();

        // ---- conversion phase: A fp32 stage -> A' bf16 (+ fused sums, once per element)
        {
            const float* As = reinterpret_cast<const float*>(smem + s * ASZ);
            char* Ap = smem + APOFF;
#pragma unroll
            for (int i = 0; i < 4; i++) {
                const int r = cv_r[i];
                const float4 v = *reinterpret_cast<const float4*>(As + r * A_STRIDE_F + cv_c * 4);
                abs_acc   += fabsf(v.x) + fabsf(v.y) + fabsf(v.z) + fabsf(v.w);
                plain_acc += (v.x + v.y) + (v.z + v.w);
                uint2 u;
                u.x = pack_bf16x2(v.x, v.y);
                u.y = pack_bf16x2(v.z, v.w);
                *reinterpret_cast<uint2*>(Ap + (r * P_STRIDE_H + cv_c * 4) * 2) = u;
            }
        }
        __syncthreads();

        // ---- mma phase: ldmatrix fragments + HMMA
        const uint32_t b_base = b_base0 + (uint32_t)(s * BSZ);
#pragma unroll
        for (int kf = 0; kf < 4; kf++) {
            uint32_t bfr[4][4];
#pragma unroll
            for (int nip = 0; nip < 4; nip++)
                ldm_x4(bfr[nip], b_base + (uint32_t)(((nip * 16) * P_STRIDE_H + kf * 16) * 2));
            uint32_t afr[2][4];
#pragma unroll
            for (int mi = 0; mi < 2; mi++)
                ldm_x4(afr[mi], a_base + (uint32_t)(((mi * 16) * P_STRIDE_H + kf * 16) * 2));
#pragma unroll
            for (int mi = 0; mi < 2; mi++)
#pragma unroll
                for (int ni = 0; ni < 8; ni++)
                    mma_16816(acc[mi][ni], afr[mi],
                              bfr[ni >> 1][ni & 1], bfr[ni >> 1][(ni & 1) + 2]);
        }
        __syncthreads();

        if (it + 2 < NIT) rdl_issue(it + 2, tid, sb, adj, row0, kbase);
    }

    // contraction: sem += out[m][d] * ehat[m][d]   (ehat[m][d] = g_ehatT[d][m])
    float sem_acc = 0.f;
#pragma unroll
    for (int mi = 0; mi < 2; mi++)
#pragma unroll
        for (int ni = 0; ni < 8; ni++) {
            const int m0 = row0 + 32 * mq + 16 * mi + g;
            const int d0 = 64 * dq + 8 * ni + 2 * c;
            const float e00 = __bfloat162float(g_ehatT[(size_t)d0 * NN + m0]);
            const float e01 = __bfloat162float(g_ehatT[(size_t)(d0 + 1) * NN + m0]);
            const float e10 = __bfloat162float(g_ehatT[(size_t)d0 * NN + m0 + 8]);
            const float e11 = __bfloat162float(g_ehatT[(size_t)(d0 + 1) * NN + m0 + 8]);
            sem_acc += acc[mi][ni][0] * e00 + acc[mi][ni][1] * e01
                     + acc[mi][ni][2] * e10 + acc[mi][ni][3] * e11;
        }

    // block reduce sem/abs/plain
#pragma unroll
    for (int o = 16; o; o >>= 1) {
        sem_acc   += __shfl_xor_sync(0xffffffffu, sem_acc, o);
        abs_acc   += __shfl_xor_sync(0xffffffffu, abs_acc, o);
        plain_acc += __shfl_xor_sync(0xffffffffu, plain_acc, o);
    }
    float* red = reinterpret_cast<float*>(smem);
    __syncthreads();
    if (lane == 0) { red[wid] = sem_acc; red[16 + wid] = abs_acc; red[32 + wid] = plain_acc; }
    __syncthreads();
    if (tid == 0) {
        float s2 = 0.f, a2 = 0.f, p2 = 0.f;
#pragma unroll
        for (int w = 0; w < 16; w++) { s2 += red[w]; a2 += red[16 + w]; p2 += red[32 + w]; }
        g_psem[blockIdx.x] = s2; g_pabs[blockIdx.x] = a2; g_pplain[blockIdx.x] = p2;
    }
}

// ---------------- kernel 4: combine ----------------
__global__ void rdl_combine(float* __restrict__ out) {
    const int tid = threadIdx.x, lane = tid & 31, wid = tid >> 5;
    __shared__ float red[4][8];
    float ce = 0.f, sem = 0.f, ab = 0.f, pl = 0.f;
    for (int i = tid; i < B_ROWS; i += 256) ce += g_ce[i];
    for (int i = tid; i < NCTA; i += 256) { sem += g_psem[i]; ab += g_pabs[i]; pl += g_pplain[i]; }
#pragma unroll
    for (int o = 16; o; o >>= 1) {
        ce  += __shfl_xor_sync(0xffffffffu, ce, o);
        sem += __shfl_xor_sync(0xffffffffu, sem, o);
        ab  += __shfl_xor_sync(0xffffffffu, ab, o);
        pl  += __shfl_xor_sync(0xffffffffu, pl, o);
    }
    if (lane == 0) { red[0][wid] = ce; red[1][wid] = sem; red[2][wid] = ab; red[3][wid] = pl; }
    __syncthreads();
    if (tid == 0) {
        float tce = 0.f, tsem = 0.f, tab = 0.f, tpl = 0.f;
#pragma unroll
        for (int w = 0; w < 8; w++) {
            tce += red[0][w]; tsem += red[1][w]; tab += red[2][w]; tpl += red[3][w];
        }
        const float invB  = 1.0f / (float)B_ROWS;
        const float invN2 = 1.0f / ((float)NN * (float)NN);
        const float l_task   = tce * invB;
        const float l_sparse = tab * invN2;
        const float l_sem    = (tpl - tsem) * invN2;
        out[0] = 1.0f * l_task + 0.01f * l_sparse + 0.1f * l_sem;
    }
}

// ---------------- launch ----------------
extern "C" void kernel_launch(void* const* d_in, const int* in_sizes, int n_in,
                              void* d_out, int out_size) {
    const float* pred = nullptr; const void* tgt = nullptr;
    const float* adj  = nullptr; const float* emb = nullptr;
    for (int i = 0; i < n_in; i++) {
        switch (in_sizes[i]) {
            case B_ROWS * C_CLS:     pred = (const float*)d_in[i]; break;
            case B_ROWS:             tgt  = d_in[i];               break;
            case NN * NN:            adj  = (const float*)d_in[i]; break;
            case NN * DD:            emb  = (const float*)d_in[i]; break;
            default: break;
        }
    }
    float* out = (float*)d_out;
    (void)out_size;

    rdl_probe<<<1, 1024>>>((const int*)tgt);
    rdl_ce<<<B_ROWS, 256>>>(pred, tgt);
    rdl_norm<<<NN / 32, 256>>>(emb);
    cudaFuncSetAttribute(rdl_main, cudaFuncAttributeMaxDynamicSharedMemorySize, SMEM_BYTES);
    rdl_main<<<NCTA, THREADS, SMEM_BYTES>>>(adj);
    rdl_combine<<<1, 256>>>(out);
}